// round 1
// baseline (speedup 1.0000x reference)
#include <cuda_runtime.h>

// Problem shape (fixed): B=1, N=4096, H=16, D=64, C=1024
#define N_SEQ 4096
#define C_DIM 1024
#define H_HEADS 16
#define D_HEAD 64
#define ATT_SCALE 0.125f   // 1/sqrt(64)

// Scratch (allocation-free rule: __device__ globals)
__device__ float g_q[H_HEADS * N_SEQ * D_HEAD];   // [H][N][D]
__device__ float g_k[H_HEADS * N_SEQ * D_HEAD];   // [H][N][D]
__device__ float g_v[H_HEADS * N_SEQ * D_HEAD];   // [H][N][D]
__device__ float g_ao[N_SEQ * C_DIM];             // [N][C] attention output

// ---------------------------------------------------------------------------
// GEMM 1: qkv[m, o] = sum_c x[m,c] * w_qkv[o,c]   (M=4096, Nout=3072, K=1024)
// Epilogue scatters into g_q/g_k/g_v in [H][N][D] layout.
// Classic 128x128x16 SGEMM, 256 threads, 8x8 per thread.
// ---------------------------------------------------------------------------
__global__ __launch_bounds__(256, 2)
void gemm_qkv_kernel(const float* __restrict__ X, const float* __restrict__ W) {
    __shared__ float As[16][128];
    __shared__ float Bs[16][128];
    const int tid = threadIdx.x;
    const int tx = tid & 15;
    const int ty = tid >> 4;
    const int m0 = blockIdx.y * 128;
    const int o0 = blockIdx.x * 128;
    const int lr = tid >> 2;          // 0..63
    const int lc = (tid & 3) * 4;     // 0,4,8,12

    float acc[8][8];
#pragma unroll
    for (int i = 0; i < 8; ++i)
#pragma unroll
        for (int j = 0; j < 8; ++j) acc[i][j] = 0.f;

    for (int k0 = 0; k0 < C_DIM; k0 += 16) {
        float4 a0 = *(const float4*)&X[(m0 + lr) * C_DIM + k0 + lc];
        float4 a1 = *(const float4*)&X[(m0 + lr + 64) * C_DIM + k0 + lc];
        float4 b0 = *(const float4*)&W[(o0 + lr) * C_DIM + k0 + lc];
        float4 b1 = *(const float4*)&W[(o0 + lr + 64) * C_DIM + k0 + lc];
        __syncthreads();
        As[lc + 0][lr] = a0.x; As[lc + 1][lr] = a0.y;
        As[lc + 2][lr] = a0.z; As[lc + 3][lr] = a0.w;
        As[lc + 0][lr + 64] = a1.x; As[lc + 1][lr + 64] = a1.y;
        As[lc + 2][lr + 64] = a1.z; As[lc + 3][lr + 64] = a1.w;
        Bs[lc + 0][lr] = b0.x; Bs[lc + 1][lr] = b0.y;
        Bs[lc + 2][lr] = b0.z; Bs[lc + 3][lr] = b0.w;
        Bs[lc + 0][lr + 64] = b1.x; Bs[lc + 1][lr + 64] = b1.y;
        Bs[lc + 2][lr + 64] = b1.z; Bs[lc + 3][lr + 64] = b1.w;
        __syncthreads();
#pragma unroll
        for (int kk = 0; kk < 16; ++kk) {
            float ra[8], rb[8];
            *(float4*)&ra[0] = *(const float4*)&As[kk][ty * 8];
            *(float4*)&ra[4] = *(const float4*)&As[kk][ty * 8 + 4];
            *(float4*)&rb[0] = *(const float4*)&Bs[kk][tx * 8];
            *(float4*)&rb[4] = *(const float4*)&Bs[kk][tx * 8 + 4];
#pragma unroll
            for (int i = 0; i < 8; ++i)
#pragma unroll
                for (int j = 0; j < 8; ++j)
                    acc[i][j] = fmaf(ra[i], rb[j], acc[i][j]);
        }
    }

#pragma unroll
    for (int i = 0; i < 8; ++i) {
        const int m = m0 + ty * 8 + i;
#pragma unroll
        for (int j = 0; j < 8; ++j) {
            const int o = o0 + tx * 8 + j;
            const int which = o >> 10;
            const int rem = o & 1023;
            const int h = rem >> 6;
            const int d = rem & 63;
            float* dst = (which == 0) ? g_q : (which == 1) ? g_k : g_v;
            dst[(h * N_SEQ + m) * D_HEAD + d] = acc[i][j];
        }
    }
}

// ---------------------------------------------------------------------------
// Flash attention (fp32, causal). One block = one head x 64 queries.
// KV processed in tiles of 32. 256 threads: (ty 0..15) -> 4 query rows,
// S-phase: tx -> 2 key cols; PV-phase: tx -> 4 d cols.
// ---------------------------------------------------------------------------
#define BQ 64
#define KT 32
__global__ __launch_bounds__(256, 2)
void attn_kernel() {
    __shared__ float Qs[BQ][68];       // d padded to 68 (float4-aligned rows)
    __shared__ float Ks[KT][68];
    __shared__ float Vs[KT][68];
    __shared__ float Ss[BQ][KT + 1];
    const int h = blockIdx.y;
    const int qt = blockIdx.x;
    const int q0 = qt * BQ;
    const int tid = threadIdx.x;
    const int tx = tid & 15;
    const int ty = tid >> 4;
    const float* Qg = g_q + h * N_SEQ * D_HEAD;
    const float* Kg = g_k + h * N_SEQ * D_HEAD;
    const float* Vg = g_v + h * N_SEQ * D_HEAD;

    // Load Q tile (64x64 floats, float4)
    for (int i = tid; i < BQ * 16; i += 256) {
        const int r = i >> 4, c = (i & 15) * 4;
        float4 v = *(const float4*)&Qg[(q0 + r) * D_HEAD + c];
        Qs[r][c] = v.x; Qs[r][c + 1] = v.y; Qs[r][c + 2] = v.z; Qs[r][c + 3] = v.w;
    }

    float acc[4][4];
    float m_i[4], l_i[4];
#pragma unroll
    for (int i = 0; i < 4; ++i) {
        m_i[i] = -1e30f; l_i[i] = 0.f;
#pragma unroll
        for (int j = 0; j < 4; ++j) acc[i][j] = 0.f;
    }

    const int nkt = (q0 + BQ) / KT;    // causal: keys 0 .. q0+63
    for (int jt = 0; jt < nkt; ++jt) {
        const int k0 = jt * KT;
        __syncthreads();   // previous PV done before overwriting Ks/Vs/Ss
        for (int i = tid; i < KT * 16; i += 256) {
            const int r = i >> 4, c = (i & 15) * 4;
            float4 kv = *(const float4*)&Kg[(k0 + r) * D_HEAD + c];
            Ks[r][c] = kv.x; Ks[r][c + 1] = kv.y; Ks[r][c + 2] = kv.z; Ks[r][c + 3] = kv.w;
            float4 vv = *(const float4*)&Vg[(k0 + r) * D_HEAD + c];
            Vs[r][c] = vv.x; Vs[r][c + 1] = vv.y; Vs[r][c + 2] = vv.z; Vs[r][c + 3] = vv.w;
        }
        __syncthreads();

        // S = Q K^T  (thread: 4 rows x 2 cols)
        float s0[4], s1[4];
#pragma unroll
        for (int i = 0; i < 4; ++i) { s0[i] = 0.f; s1[i] = 0.f; }
#pragma unroll 16
        for (int d = 0; d < D_HEAD; ++d) {
            const float kv0 = Ks[tx * 2][d];
            const float kv1 = Ks[tx * 2 + 1][d];
#pragma unroll
            for (int i = 0; i < 4; ++i) {
                const float qv = Qs[ty * 4 + i][d];
                s0[i] = fmaf(qv, kv0, s0[i]);
                s1[i] = fmaf(qv, kv1, s1[i]);
            }
        }

        const bool diag = (k0 + KT > q0);
#pragma unroll
        for (int i = 0; i < 4; ++i) {
            const int qg = q0 + ty * 4 + i;
            float a = s0[i] * ATT_SCALE;
            float b = s1[i] * ATT_SCALE;
            if (diag) {
                if (k0 + tx * 2     > qg) a = -1e30f;
                if (k0 + tx * 2 + 1 > qg) b = -1e30f;
            }
            float mx = fmaxf(a, b);
#pragma unroll
            for (int off = 1; off < 16; off <<= 1)
                mx = fmaxf(mx, __shfl_xor_sync(0xffffffffu, mx, off));
            const float newm = fmaxf(m_i[i], mx);
            const float p0 = __expf(a - newm);
            const float p1 = __expf(b - newm);
            float rs = p0 + p1;
#pragma unroll
            for (int off = 1; off < 16; off <<= 1)
                rs += __shfl_xor_sync(0xffffffffu, rs, off);
            const float corr = __expf(m_i[i] - newm);
            l_i[i] = l_i[i] * corr + rs;
            m_i[i] = newm;
#pragma unroll
            for (int jd = 0; jd < 4; ++jd) acc[i][jd] *= corr;
            Ss[ty * 4 + i][tx * 2]     = p0;
            Ss[ty * 4 + i][tx * 2 + 1] = p1;
        }
        __syncthreads();

        // PV accumulate (thread: 4 rows x 4 d-cols)
#pragma unroll 8
        for (int k = 0; k < KT; ++k) {
            float vv[4];
#pragma unroll
            for (int jd = 0; jd < 4; ++jd) vv[jd] = Vs[k][tx * 4 + jd];
#pragma unroll
            for (int i = 0; i < 4; ++i) {
                const float p = Ss[ty * 4 + i][k];
#pragma unroll
                for (int jd = 0; jd < 4; ++jd)
                    acc[i][jd] = fmaf(p, vv[jd], acc[i][jd]);
            }
        }
    }

    // Write [N][C] layout for proj GEMM
#pragma unroll
    for (int i = 0; i < 4; ++i) {
        const float inv = 1.f / l_i[i];
        const int n = q0 + ty * 4 + i;
#pragma unroll
        for (int jd = 0; jd < 4; ++jd)
            g_ao[n * C_DIM + h * D_HEAD + tx * 4 + jd] = acc[i][jd] * inv;
    }
}

// ---------------------------------------------------------------------------
// GEMM 2: out[m, o] = sum_c g_ao[m,c] * w_proj[o,c] + b_proj[o]
// (M=4096, Nout=1024, K=1024)
// ---------------------------------------------------------------------------
__global__ __launch_bounds__(256, 2)
void gemm_proj_kernel(const float* __restrict__ W, const float* __restrict__ bias,
                      float* __restrict__ out) {
    __shared__ float As[16][128];
    __shared__ float Bs[16][128];
    const int tid = threadIdx.x;
    const int tx = tid & 15;
    const int ty = tid >> 4;
    const int m0 = blockIdx.y * 128;
    const int o0 = blockIdx.x * 128;
    const int lr = tid >> 2;
    const int lc = (tid & 3) * 4;

    float acc[8][8];
#pragma unroll
    for (int i = 0; i < 8; ++i)
#pragma unroll
        for (int j = 0; j < 8; ++j) acc[i][j] = 0.f;

    for (int k0 = 0; k0 < C_DIM; k0 += 16) {
        float4 a0 = *(const float4*)&g_ao[(m0 + lr) * C_DIM + k0 + lc];
        float4 a1 = *(const float4*)&g_ao[(m0 + lr + 64) * C_DIM + k0 + lc];
        float4 b0 = *(const float4*)&W[(o0 + lr) * C_DIM + k0 + lc];
        float4 b1 = *(const float4*)&W[(o0 + lr + 64) * C_DIM + k0 + lc];
        __syncthreads();
        As[lc + 0][lr] = a0.x; As[lc + 1][lr] = a0.y;
        As[lc + 2][lr] = a0.z; As[lc + 3][lr] = a0.w;
        As[lc + 0][lr + 64] = a1.x; As[lc + 1][lr + 64] = a1.y;
        As[lc + 2][lr + 64] = a1.z; As[lc + 3][lr + 64] = a1.w;
        Bs[lc + 0][lr] = b0.x; Bs[lc + 1][lr] = b0.y;
        Bs[lc + 2][lr] = b0.z; Bs[lc + 3][lr] = b0.w;
        Bs[lc + 0][lr + 64] = b1.x; Bs[lc + 1][lr + 64] = b1.y;
        Bs[lc + 2][lr + 64] = b1.z; Bs[lc + 3][lr + 64] = b1.w;
        __syncthreads();
#pragma unroll
        for (int kk = 0; kk < 16; ++kk) {
            float ra[8], rb[8];
            *(float4*)&ra[0] = *(const float4*)&As[kk][ty * 8];
            *(float4*)&ra[4] = *(const float4*)&As[kk][ty * 8 + 4];
            *(float4*)&rb[0] = *(const float4*)&Bs[kk][tx * 8];
            *(float4*)&rb[4] = *(const float4*)&Bs[kk][tx * 8 + 4];
#pragma unroll
            for (int i = 0; i < 8; ++i)
#pragma unroll
                for (int j = 0; j < 8; ++j)
                    acc[i][j] = fmaf(ra[i], rb[j], acc[i][j]);
        }
    }

#pragma unroll
    for (int i = 0; i < 8; ++i) {
        const int m = m0 + ty * 8 + i;
#pragma unroll
        for (int j = 0; j < 8; ++j) {
            const int o = o0 + tx * 8 + j;
            out[m * C_DIM + o] = acc[i][j] + bias[o];
        }
    }
}

// ---------------------------------------------------------------------------
extern "C" void kernel_launch(void* const* d_in, const int* in_sizes, int n_in,
                              void* d_out, int out_size) {
    const float* x      = (const float*)d_in[0];   // [1,4096,1024]
    const float* w_qkv  = (const float*)d_in[1];   // [3072,1024]
    const float* w_proj = (const float*)d_in[2];   // [1024,1024]
    const float* b_proj = (const float*)d_in[3];   // [1024]
    float* out = (float*)d_out;                    // [1,4096,1024]

    gemm_qkv_kernel<<<dim3(3 * C_DIM / 128, N_SEQ / 128), 256>>>(x, w_qkv);
    attn_kernel<<<dim3(N_SEQ / BQ, H_HEADS), 256>>>();
    gemm_proj_kernel<<<dim3(C_DIM / 128, N_SEQ / 128), 256>>>(w_proj, b_proj, out);
}

// round 4
// speedup vs baseline: 2.7720x; 2.7720x over previous
#include <cuda_runtime.h>

// Problem shape (fixed): B=1, N=4096, H=16, D=64, C=1024
#define N_SEQ 4096
#define C_DIM 1024
#define H_HEADS 16
#define D_HEAD 64
#define ATT_SCALE 0.125f

// Scratch (allocation-free rule)
__device__ float g_q[H_HEADS * N_SEQ * D_HEAD];   // [H][N][D]
__device__ float g_k[H_HEADS * N_SEQ * D_HEAD];
__device__ float g_v[H_HEADS * N_SEQ * D_HEAD];
__device__ float g_ao[N_SEQ * C_DIM];             // [N][C]

// ---- tf32 helpers ---------------------------------------------------------
__device__ __forceinline__ unsigned f2tf(float f) {
    unsigned u;
    asm("cvt.rna.tf32.f32 %0, %1;" : "=r"(u) : "f"(f));
    return u;
}
__device__ __forceinline__ void mma_tf32(float* c, unsigned a0, unsigned a1,
                                         unsigned a2, unsigned a3,
                                         unsigned b0, unsigned b1) {
    asm volatile(
        "mma.sync.aligned.m16n8k8.row.col.f32.tf32.tf32.f32 "
        "{%0,%1,%2,%3}, {%4,%5,%6,%7}, {%8,%9}, {%0,%1,%2,%3};"
        : "+f"(c[0]), "+f"(c[1]), "+f"(c[2]), "+f"(c[3])
        : "r"(a0), "r"(a1), "r"(a2), "r"(a3), "r"(b0), "r"(b1));
}

// ---------------------------------------------------------------------------
// tf32 GEMM: out[m,o] = sum_c A[m,c] * W[o,c]. 128x128x16 tile, 256 thr.
// EPI=0: A = x (host arg), scatter qkv into g_q/g_k/g_v.
// EPI=1: A = g_ao (device symbol, resolved IN KERNEL), proj + bias -> out.
// Smem stride 136 (== 8 mod 32): frag loads bank 8tg+g bijective -> CF.
// ---------------------------------------------------------------------------
#define GS 136
template <int EPI>
__global__ __launch_bounds__(256, 2)
void gemm_tf32_kernel(const float* __restrict__ A_in, const float* __restrict__ W,
                      const float* __restrict__ bias, float* __restrict__ out) {
    // Device-side symbol resolution: __device__ arrays must not be passed
    // as kernel args from host code (host shadow address != device address).
    const float* __restrict__ A = (EPI == 0) ? A_in : (const float*)g_ao;

    __shared__ unsigned As[16][GS];   // [k][m]
    __shared__ unsigned Bs[16][GS];   // [k][o]
    const int tid = threadIdx.x;
    const int warp = tid >> 5;
    const int lane = tid & 31;
    const int g = lane >> 2;       // 0..7
    const int tg = lane & 3;       // 0..3
    const int wm = (warp & 1) * 64;    // 2 warps along M
    const int wn = (warp >> 1) * 32;   // 4 warps along N
    const int m0 = blockIdx.y * 128;
    const int o0 = blockIdx.x * 128;
    const int lr = tid >> 2;           // 0..63
    const int lc = (tid & 3) * 4;

    float acc[4][4][4];   // [mt][nt][c-frag]
#pragma unroll
    for (int i = 0; i < 4; ++i)
#pragma unroll
        for (int j = 0; j < 4; ++j)
#pragma unroll
            for (int c = 0; c < 4; ++c) acc[i][j][c] = 0.f;

    for (int k0 = 0; k0 < C_DIM; k0 += 16) {
        float4 a0 = *(const float4*)&A[(m0 + lr) * C_DIM + k0 + lc];
        float4 a1 = *(const float4*)&A[(m0 + lr + 64) * C_DIM + k0 + lc];
        float4 b0 = *(const float4*)&W[(o0 + lr) * C_DIM + k0 + lc];
        float4 b1 = *(const float4*)&W[(o0 + lr + 64) * C_DIM + k0 + lc];
        __syncthreads();
        As[lc + 0][lr] = f2tf(a0.x); As[lc + 1][lr] = f2tf(a0.y);
        As[lc + 2][lr] = f2tf(a0.z); As[lc + 3][lr] = f2tf(a0.w);
        As[lc + 0][lr + 64] = f2tf(a1.x); As[lc + 1][lr + 64] = f2tf(a1.y);
        As[lc + 2][lr + 64] = f2tf(a1.z); As[lc + 3][lr + 64] = f2tf(a1.w);
        Bs[lc + 0][lr] = f2tf(b0.x); Bs[lc + 1][lr] = f2tf(b0.y);
        Bs[lc + 2][lr] = f2tf(b0.z); Bs[lc + 3][lr] = f2tf(b0.w);
        Bs[lc + 0][lr + 64] = f2tf(b1.x); Bs[lc + 1][lr + 64] = f2tf(b1.y);
        Bs[lc + 2][lr + 64] = f2tf(b1.z); Bs[lc + 3][lr + 64] = f2tf(b1.w);
        __syncthreads();
#pragma unroll
        for (int ks = 0; ks < 16; ks += 8) {
            unsigned af[4][4];
#pragma unroll
            for (int mt = 0; mt < 4; ++mt) {
                const int rb = wm + mt * 16;
                af[mt][0] = As[ks + tg][rb + g];
                af[mt][1] = As[ks + tg][rb + g + 8];
                af[mt][2] = As[ks + tg + 4][rb + g];
                af[mt][3] = As[ks + tg + 4][rb + g + 8];
            }
#pragma unroll
            for (int nt = 0; nt < 4; ++nt) {
                const unsigned bf0 = Bs[ks + tg][wn + nt * 8 + g];
                const unsigned bf1 = Bs[ks + tg + 4][wn + nt * 8 + g];
#pragma unroll
                for (int mt = 0; mt < 4; ++mt)
                    mma_tf32(acc[mt][nt], af[mt][0], af[mt][1], af[mt][2],
                             af[mt][3], bf0, bf1);
            }
        }
    }

    // Epilogue: thread owns (row g / g+8, col pair 2tg,2tg+1) per tile
#pragma unroll
    for (int mt = 0; mt < 4; ++mt) {
        const int r0 = m0 + wm + mt * 16 + g;
#pragma unroll
        for (int nt = 0; nt < 4; ++nt) {
            const int o = o0 + wn + nt * 8 + 2 * tg;   // even
            if (EPI == 0) {
                const int which = o >> 10;
                const int rem = o & 1023;
                const int h = rem >> 6;
                const int d = rem & 63;
                float* dst = (which == 0) ? g_q : (which == 1) ? g_k : g_v;
                *(float2*)&dst[(h * N_SEQ + r0) * D_HEAD + d] =
                    make_float2(acc[mt][nt][0], acc[mt][nt][1]);
                *(float2*)&dst[(h * N_SEQ + r0 + 8) * D_HEAD + d] =
                    make_float2(acc[mt][nt][2], acc[mt][nt][3]);
            } else {
                const float bx = bias[o], by = bias[o + 1];
                *(float2*)&out[r0 * C_DIM + o] =
                    make_float2(acc[mt][nt][0] + bx, acc[mt][nt][1] + by);
                *(float2*)&out[(r0 + 8) * C_DIM + o] =
                    make_float2(acc[mt][nt][2] + bx, acc[mt][nt][3] + by);
            }
        }
    }
}

// ---------------------------------------------------------------------------
// Flash attention, tf32 tensor cores. 128 threads = 4 warps; BQ=64 (16 q/warp),
// KT=32. S kept in registers through online softmax; P routed via smem.
// ---------------------------------------------------------------------------
#define BQ 64
#define KT 32
__global__ __launch_bounds__(128, 4)
void attn_kernel() {
    __shared__ unsigned Qs[BQ][68];    // [q][d]
    __shared__ unsigned Ks[KT][68];    // [key][d]
    __shared__ unsigned Vs[KT][72];    // [key][d]
    __shared__ unsigned Ps[BQ][36];    // [q][k]

    const int h = blockIdx.y;
    const int q0 = blockIdx.x * BQ;
    const int tid = threadIdx.x;
    const int warp = tid >> 5;
    const int lane = tid & 31;
    const int g = lane >> 2;
    const int tg = lane & 3;
    const int wq = warp * 16;          // warp's q-row base in tile

    const float* Qg = g_q + h * N_SEQ * D_HEAD;
    const float* Kg = g_k + h * N_SEQ * D_HEAD;
    const float* Vg = g_v + h * N_SEQ * D_HEAD;

    // Load Q tile (64x64)
    for (int i = tid; i < BQ * 16; i += 128) {
        const int r = i >> 4, c = (i & 15) * 4;
        float4 v = *(const float4*)&Qg[(q0 + r) * D_HEAD + c];
        Qs[r][c] = f2tf(v.x); Qs[r][c + 1] = f2tf(v.y);
        Qs[r][c + 2] = f2tf(v.z); Qs[r][c + 3] = f2tf(v.w);
    }

    float o_acc[8][4];                 // [d-tile][c-frag]
#pragma unroll
    for (int dt = 0; dt < 8; ++dt)
#pragma unroll
        for (int c = 0; c < 4; ++c) o_acc[dt][c] = 0.f;
    float m0_ = -1e30f, m1_ = -1e30f, l0_ = 0.f, l1_ = 0.f;

    const int nkt = (q0 + BQ) / KT;
    for (int jt = 0; jt < nkt; ++jt) {
        const int k0 = jt * KT;
        __syncthreads();
        for (int i = tid; i < KT * 16; i += 128) {
            const int r = i >> 4, c = (i & 15) * 4;
            float4 kv = *(const float4*)&Kg[(k0 + r) * D_HEAD + c];
            Ks[r][c] = f2tf(kv.x); Ks[r][c + 1] = f2tf(kv.y);
            Ks[r][c + 2] = f2tf(kv.z); Ks[r][c + 3] = f2tf(kv.w);
            float4 vv = *(const float4*)&Vg[(k0 + r) * D_HEAD + c];
            Vs[r][c] = f2tf(vv.x); Vs[r][c + 1] = f2tf(vv.y);
            Vs[r][c + 2] = f2tf(vv.z); Vs[r][c + 3] = f2tf(vv.w);
        }
        __syncthreads();

        // ---- S = Q K^T for this warp's 16 rows x 32 keys, in registers
        float s[4][4];
#pragma unroll
        for (int nt = 0; nt < 4; ++nt)
#pragma unroll
            for (int c = 0; c < 4; ++c) s[nt][c] = 0.f;
#pragma unroll
        for (int ks = 0; ks < 8; ++ks) {
            const int kc = ks * 8;
            const unsigned aq0 = Qs[wq + g][kc + tg];
            const unsigned aq1 = Qs[wq + g + 8][kc + tg];
            const unsigned aq2 = Qs[wq + g][kc + tg + 4];
            const unsigned aq3 = Qs[wq + g + 8][kc + tg + 4];
#pragma unroll
            for (int nt = 0; nt < 4; ++nt) {
                const unsigned bk0 = Ks[nt * 8 + g][kc + tg];
                const unsigned bk1 = Ks[nt * 8 + g][kc + tg + 4];
                mma_tf32(s[nt], aq0, aq1, aq2, aq3, bk0, bk1);
            }
        }

        // ---- mask + online softmax (rows r0 = q0+wq+g, r1 = r0+8)
        const int r0 = q0 + wq + g;
        const int r1 = r0 + 8;
        float mx0 = -1e30f, mx1 = -1e30f;
#pragma unroll
        for (int nt = 0; nt < 4; ++nt) {
            const int c0 = k0 + nt * 8 + 2 * tg;
            const int c1 = c0 + 1;
            s[nt][0] = (c0 > r0) ? -1e30f : s[nt][0] * ATT_SCALE;
            s[nt][1] = (c1 > r0) ? -1e30f : s[nt][1] * ATT_SCALE;
            s[nt][2] = (c0 > r1) ? -1e30f : s[nt][2] * ATT_SCALE;
            s[nt][3] = (c1 > r1) ? -1e30f : s[nt][3] * ATT_SCALE;
            mx0 = fmaxf(mx0, fmaxf(s[nt][0], s[nt][1]));
            mx1 = fmaxf(mx1, fmaxf(s[nt][2], s[nt][3]));
        }
        mx0 = fmaxf(mx0, __shfl_xor_sync(0xffffffffu, mx0, 1));
        mx0 = fmaxf(mx0, __shfl_xor_sync(0xffffffffu, mx0, 2));
        mx1 = fmaxf(mx1, __shfl_xor_sync(0xffffffffu, mx1, 1));
        mx1 = fmaxf(mx1, __shfl_xor_sync(0xffffffffu, mx1, 2));

        const float nm0 = fmaxf(m0_, mx0);
        const float nm1 = fmaxf(m1_, mx1);
        const float corr0 = __expf(m0_ - nm0);
        const float corr1 = __expf(m1_ - nm1);
        m0_ = nm0; m1_ = nm1;

        float rs0 = 0.f, rs1 = 0.f;
#pragma unroll
        for (int nt = 0; nt < 4; ++nt) {
            const float p00 = __expf(s[nt][0] - nm0);
            const float p01 = __expf(s[nt][1] - nm0);
            const float p10 = __expf(s[nt][2] - nm1);
            const float p11 = __expf(s[nt][3] - nm1);
            rs0 += p00 + p01;
            rs1 += p10 + p11;
            const int cc = nt * 8 + 2 * tg;
            Ps[wq + g][cc] = f2tf(p00); Ps[wq + g][cc + 1] = f2tf(p01);
            Ps[wq + g + 8][cc] = f2tf(p10); Ps[wq + g + 8][cc + 1] = f2tf(p11);
        }
        rs0 += __shfl_xor_sync(0xffffffffu, rs0, 1);
        rs0 += __shfl_xor_sync(0xffffffffu, rs0, 2);
        rs1 += __shfl_xor_sync(0xffffffffu, rs1, 1);
        rs1 += __shfl_xor_sync(0xffffffffu, rs1, 2);
        l0_ = l0_ * corr0 + rs0;
        l1_ = l1_ * corr1 + rs1;

#pragma unroll
        for (int dt = 0; dt < 8; ++dt) {
            o_acc[dt][0] *= corr0; o_acc[dt][1] *= corr0;
            o_acc[dt][2] *= corr1; o_acc[dt][3] *= corr1;
        }
        __syncwarp();   // Ps rows wq..wq+15 written & read by this warp only

        // ---- O += P V
#pragma unroll
        for (int ks = 0; ks < 4; ++ks) {
            const int kc = ks * 8;
            const unsigned ap0 = Ps[wq + g][kc + tg];
            const unsigned ap1 = Ps[wq + g + 8][kc + tg];
            const unsigned ap2 = Ps[wq + g][kc + tg + 4];
            const unsigned ap3 = Ps[wq + g + 8][kc + tg + 4];
#pragma unroll
            for (int dt = 0; dt < 8; ++dt) {
                const unsigned bv0 = Vs[kc + tg][dt * 8 + g];
                const unsigned bv1 = Vs[kc + tg + 4][dt * 8 + g];
                mma_tf32(o_acc[dt], ap0, ap1, ap2, ap3, bv0, bv1);
            }
        }
    }

    // ---- normalize + write [N][C]
    const float inv0 = 1.f / l0_;
    const float inv1 = 1.f / l1_;
    const int n0 = q0 + wq + g;
#pragma unroll
    for (int dt = 0; dt < 8; ++dt) {
        const int col = h * D_HEAD + dt * 8 + 2 * tg;
        *(float2*)&g_ao[n0 * C_DIM + col] =
            make_float2(o_acc[dt][0] * inv0, o_acc[dt][1] * inv0);
        *(float2*)&g_ao[(n0 + 8) * C_DIM + col] =
            make_float2(o_acc[dt][2] * inv1, o_acc[dt][3] * inv1);
    }
}

// ---------------------------------------------------------------------------
extern "C" void kernel_launch(void* const* d_in, const int* in_sizes, int n_in,
                              void* d_out, int out_size) {
    const float* x      = (const float*)d_in[0];
    const float* w_qkv  = (const float*)d_in[1];
    const float* w_proj = (const float*)d_in[2];
    const float* b_proj = (const float*)d_in[3];
    float* out = (float*)d_out;

    gemm_tf32_kernel<0><<<dim3(3 * C_DIM / 128, N_SEQ / 128), 256>>>(
        x, w_qkv, nullptr, nullptr);
    attn_kernel<<<dim3(N_SEQ / BQ, H_HEADS), 128>>>();
    gemm_tf32_kernel<1><<<dim3(C_DIM / 128, N_SEQ / 128), 256>>>(
        nullptr, w_proj, b_proj, out);
}